// round 8
// baseline (speedup 1.0000x reference)
#include <cuda_runtime.h>
#include <cuda_fp16.h>
#include <cstdint>

#define VOCABSZ 32000
#define EMBD    1024
#define HID     1024
#define G4      4096
#define NB      64
#define LSEQ    512
#define NCTA    128

// ---------------- device scratch (static; no cudaMalloc allowed) ----------------
__device__ __half g_Eb[(size_t)VOCABSZ * EMBD];          // E as fp16 (64 MB)
__device__ __half g_Bx[(size_t)G4 * 1024];               // W_x^T, [colp][k], gate-permuted (8 MB)
__device__ float  g_bias[G4];                            // permuted bias
__device__ float  g_Gx[(size_t)LSEQ * G4 * NB];          // x-gates, [t][cta][n][loc32]
__device__ __half g_Hbuf[2][NB * HID];                   // H double buffer (fp16)
__device__ int    g_bar[2 * LSEQ];                       // per-group per-step counters

// gate-column permutation: colp = cta*32 + loc ; loc>>3 = gate (i,f,o,g), loc&7 = unit
__device__ __forceinline__ int perm_row(int colp) {
    int cta = colp >> 5, loc = colp & 31;
    return ((loc >> 3) << 10) + (cta << 3) + (loc & 7);
}

// ---------------- mma / ldmatrix / cp.async helpers -----------------------------
__device__ __forceinline__ unsigned smem_u32(const void* p) {
    return (unsigned)__cvta_generic_to_shared(p);
}
__device__ __forceinline__ void ldmatrix_x4(unsigned* r, unsigned addr) {
    asm volatile("ldmatrix.sync.aligned.m8n8.x4.shared.b16 {%0,%1,%2,%3}, [%4];"
                 : "=r"(r[0]), "=r"(r[1]), "=r"(r[2]), "=r"(r[3]) : "r"(addr));
}
__device__ __forceinline__ void ldmatrix_x2(unsigned* r, unsigned addr) {
    asm volatile("ldmatrix.sync.aligned.m8n8.x2.shared.b16 {%0,%1}, [%2];"
                 : "=r"(r[0]), "=r"(r[1]) : "r"(addr));
}
__device__ __forceinline__ void mma16816(float* d, const unsigned* a, unsigned b0, unsigned b1) {
    asm volatile("mma.sync.aligned.m16n8k16.row.col.f32.f16.f16.f32 "
                 "{%0,%1,%2,%3}, {%4,%5,%6,%7}, {%8,%9}, {%0,%1,%2,%3};"
                 : "+f"(d[0]), "+f"(d[1]), "+f"(d[2]), "+f"(d[3])
                 : "r"(a[0]), "r"(a[1]), "r"(a[2]), "r"(a[3]), "r"(b0), "r"(b1));
}
__device__ __forceinline__ void cp16(void* s, const void* g) {
    asm volatile("cp.async.cg.shared.global [%0], [%1], 16;"
                 :: "r"(smem_u32(s)), "l"(g) : "memory");
}
__device__ __forceinline__ void cp_commit() { asm volatile("cp.async.commit_group;" ::: "memory"); }
template <int N>
__device__ __forceinline__ void cp_wait() { asm volatile("cp.async.wait_group %0;" :: "n"(N) : "memory"); }

__device__ __forceinline__ float sigf(float x) { return 1.0f / (1.0f + expf(-x)); }

// ---------------- prep: E -> fp16 ------------------------------------------------
__global__ __launch_bounds__(256) void k_cvt_e(const float* __restrict__ E) {
    size_t total8 = (size_t)VOCABSZ * EMBD / 8;
    size_t stride = (size_t)gridDim.x * blockDim.x;
    for (size_t i = (size_t)blockIdx.x * blockDim.x + threadIdx.x; i < total8; i += stride) {
        const float4* s = (const float4*)(E + i * 8);
        float4 v0 = s[0], v1 = s[1];
        __half2 h0 = __floats2half2_rn(v0.x, v0.y);
        __half2 h1 = __floats2half2_rn(v0.z, v0.w);
        __half2 h2 = __floats2half2_rn(v1.x, v1.y);
        __half2 h3 = __floats2half2_rn(v1.z, v1.w);
        uint4 o;
        o.x = *(unsigned*)&h0; o.y = *(unsigned*)&h1;
        o.z = *(unsigned*)&h2; o.w = *(unsigned*)&h3;
        ((uint4*)g_Eb)[i] = o;
    }
}

// ---------------- prep: pack Bx, bias, reset barriers & H0 -----------------------
__global__ __launch_bounds__(256) void k_pack(const float* __restrict__ W,
                                              const float* __restrict__ Wb) {
    int i0 = blockIdx.x * blockDim.x + threadIdx.x;
    int stride = gridDim.x * blockDim.x;
    for (int idx = i0; idx < G4 * 1024; idx += stride) {
        int colp = idx >> 10, k = idx & 1023;
        g_Bx[idx] = __float2half(W[(size_t)perm_row(colp) * 2048 + 1024 + k]);
    }
    for (int idx = i0; idx < G4; idx += stride) g_bias[idx] = Wb[perm_row(idx)];
    for (int idx = i0; idx < 2 * LSEQ; idx += stride) g_bar[idx] = 0;
    for (int idx = i0; idx < NB * HID; idx += stride) g_Hbuf[0][idx] = __float2half(0.0f);
}

// ---------------- phase 1: Gx = embed(X) @ Wx^T + b (R5-proven) -------------------
#define GX_STG  4
#define GX_STR  40
#define GX_TILE (128 * GX_STR)
#define GX_SMEM (GX_STG * 2 * GX_TILE * 2)       // 81920 B

__global__ __launch_bounds__(256, 2) void k_gx(const int* __restrict__ X) {
    extern __shared__ __align__(16) __half dsm[];
    __half* As = dsm;
    __half* Bs = dsm + GX_STG * GX_TILE;
    __shared__ int   toks[128];
    __shared__ float bsm[128];

    int tid = threadIdx.x, lane = tid & 31, warp = tid >> 5;
    int wm = warp >> 1, wn = warp & 1;
    int mblk = blockIdx.y * 128, nblk = blockIdx.x * 128;

    if (tid < 128) {
        int m = mblk + tid;                      // m = t*64 + n
        toks[tid] = X[(m & 63) * LSEQ + (m >> 6)];
        bsm[tid] = g_bias[nblk + tid];
    }
    __syncthreads();

    auto issue = [&](int c) {
        __half* Ab = As + (c & (GX_STG - 1)) * GX_TILE;
        __half* Bb = Bs + (c & (GX_STG - 1)) * GX_TILE;
        int k0 = c * 32;
#pragma unroll
        for (int i = 0; i < 2; ++i) {
            int idx = tid + i * 256;
            int row = idx >> 2, q = idx & 3;
            cp16(Ab + row * GX_STR + q * 8,
                 &g_Eb[(size_t)toks[row] * EMBD + k0 + q * 8]);
        }
#pragma unroll
        for (int i = 0; i < 2; ++i) {
            int idx = tid + i * 256;
            int row = idx >> 2, q = idx & 3;
            cp16(Bb + row * GX_STR + q * 8,
                 &g_Bx[(size_t)(nblk + row) * 1024 + k0 + q * 8]);
        }
        cp_commit();
    };

    float acc[2][8][4];
#pragma unroll
    for (int a = 0; a < 2; ++a)
#pragma unroll
        for (int b = 0; b < 8; ++b)
#pragma unroll
            for (int c = 0; c < 4; ++c) acc[a][b][c] = 0.0f;

    issue(0); issue(1); issue(2);

    for (int c = 0; c < 32; ++c) {
        if (c < 30)       cp_wait<2>();
        else if (c == 30) cp_wait<1>();
        else              cp_wait<0>();
        __syncthreads();

        if (c + 3 < 32) issue(c + 3);

        const __half* Ab = As + (c & (GX_STG - 1)) * GX_TILE;
        const __half* Bb = Bs + (c & (GX_STG - 1)) * GX_TILE;
#pragma unroll
        for (int ks = 0; ks < 2; ++ks) {
            unsigned a[2][4];
#pragma unroll
            for (int mt = 0; mt < 2; ++mt)
                ldmatrix_x4(a[mt], smem_u32(Ab + (wm * 32 + mt * 16 + (lane & 15)) * GX_STR
                                               + ks * 16 + (lane >> 4) * 8));
#pragma unroll
            for (int nt = 0; nt < 8; ++nt) {
                unsigned b[2];
                ldmatrix_x2(b, smem_u32(Bb + (wn * 64 + nt * 8 + (lane & 7)) * GX_STR
                                           + ks * 16 + ((lane >> 3) & 1) * 8));
                mma16816(acc[0][nt], a[0], b[0], b[1]);
                mma16816(acc[1][nt], a[1], b[0], b[1]);
            }
        }
    }

    // epilogue: add bias, store Gx[t][cta][n][loc32]
#pragma unroll
    for (int mt = 0; mt < 2; ++mt) {
#pragma unroll
        for (int nt = 0; nt < 8; ++nt) {
            int mrow = mblk + wm * 32 + mt * 16 + (lane >> 2);
            int cloc = wn * 64 + nt * 8 + ((lane & 3) << 1);
            int colp = nblk + cloc;
            float b0 = bsm[cloc], b1 = bsm[cloc + 1];
            const float* c = acc[mt][nt];
#pragma unroll
            for (int rr = 0; rr < 2; ++rr) {
                int m = mrow + rr * 8;
                int t = m >> 6, n = m & 63;
                size_t off = (((size_t)t * NCTA + (colp >> 5)) * NB + n) * 32 + (colp & 31);
                float2 v; v.x = c[rr * 2] + b0; v.y = c[rr * 2 + 1] + b1;
                *(float2*)&g_Gx[off] = v;
            }
        }
    }
}

// ---------------- phase 2: persistent recurrent kernel, dual-group interleave ----
// 128 CTAs x 256 threads. CTA c owns 32 gate cols (8 units) for BOTH batch groups
// (g0 rows 0-31, g1 rows 32-63), anti-phased to hide load/barrier latency.
// Warp (wk 0..3 K-quarter, wm 0..1 row-half). Exchange buffers alias each group's Hs.
#define HS_STRIDE 1032
#define SM_H0 0
#define SM_H1 (32 * HS_STRIDE * 2)                 // 66048
#define SM_WS (2 * 32 * HS_STRIDE * 2)             // 132096
#define SMEM_REC (SM_WS + 32 * HS_STRIDE * 2)      // 198144

__global__ void __launch_bounds__(256, 1) k_rec(const float* __restrict__ W,
                                                float* __restrict__ out) {
    extern __shared__ __align__(16) char smem[];
    __half (*Hs0)[HS_STRIDE] = (__half(*)[HS_STRIDE])(smem + SM_H0);
    __half (*Hs1)[HS_STRIDE] = (__half(*)[HS_STRIDE])(smem + SM_H1);
    __half (*Ws)[HS_STRIDE]  = (__half(*)[HS_STRIDE])(smem + SM_WS);
    float* gsm0 = (float*)(smem + SM_H0);          // [4][32][33] floats, aliases Hs0
    float* gsm1 = (float*)(smem + SM_H1);          // aliases Hs1

    int cta = blockIdx.x;
    int tid = threadIdx.x, lane = tid & 31, warp = tid >> 5;
    int wk = warp >> 1;                            // K-quarter 0..3
    int wm = warp & 1;                             // row-half 0..1
    int cb = wk * 256;                             // K base
    int rm = wm * 16;                              // row base (within group)

    // resident weight slice (R4-proven): Ws[loc][k] = W[perm(cta*32+loc)][k] (h-part)
    for (int idx = tid; idx < 32 * 1024; idx += 256) {
        int loc = idx >> 10, k = idx & 1023;
        int wrow = ((loc >> 3) << 10) + (cta << 3) + (loc & 7);
        Ws[loc][k] = __float2half(W[(size_t)wrow * 2048 + k]);
    }
    __syncthreads();

    // per-thread cell: (row = tid>>3 in 0..31, unit j = tid&7); one cell per group
    int row = tid >> 3, j = tid & 7;
    float C[2] = {0.0f, 0.0f};
    const float* gxbase = g_Gx + (size_t)cta * NB * 32;

    // stage loader: warp loads rows [rm,+16) x K [cb,+256) of group g's H
    auto issue = [&](int g, int tpar) {
        const __half* Hg = g_Hbuf[tpar] + (size_t)g * 32 * 1024;
        __half (*Hd)[HS_STRIDE] = g ? Hs1 : Hs0;
#pragma unroll
        for (int i = 0; i < 16; ++i) {
            int r = rm + i;
            cp16(&Hd[r][cb + lane * 8], Hg + r * 1024 + cb + lane * 8);
        }
        cp_commit();
    };

    auto mmaphase = [&](__half (*Hg)[HS_STRIDE], float (*acc)[4]) {
#pragma unroll 4
        for (int kt = 0; kt < 16; ++kt) {
            int k0 = cb + kt * 16;
            unsigned a[4];
            ldmatrix_x4(a, smem_u32(&Hg[rm + (lane & 15)][k0 + (lane >> 4) * 8]));
#pragma unroll
            for (int bg = 0; bg < 2; ++bg) {
                unsigned b[4];
                ldmatrix_x4(b, smem_u32(&Ws[bg * 16 + ((lane >> 4) << 3) + (lane & 7)]
                                          [k0 + ((lane >> 3) & 1) * 8]));
                mma16816(acc[bg * 2],     a, b[0], b[1]);
                mma16816(acc[bg * 2 + 1], a, b[2], b[3]);
            }
        }
    };

    auto storegsm = [&](float* gbase, float (*acc)[4]) {
        float* gp = gbase + wk * 1056;             // quarter stride 32*33
        int mr = rm + (lane >> 2);
        int nc = (lane & 3) << 1;
#pragma unroll
        for (int ng = 0; ng < 4; ++ng) {
            const float* cc = acc[ng];
            int n = ng * 8 + nc;
            gp[mr * 33 + n]           = cc[0];
            gp[mr * 33 + n + 1]       = cc[1];
            gp[(mr + 8) * 33 + n]     = cc[2];
            gp[(mr + 8) * 33 + n + 1] = cc[3];
        }
    };

    auto cell = [&](int g, const float* gxq, int t) {
        const float* gb = g ? gsm1 : gsm0;
        float s[4];
#pragma unroll
        for (int q = 0; q < 4; ++q) {
            float v = gxq[q];
            int base = row * 33 + q * 8 + j;
#pragma unroll
            for (int kq = 0; kq < 4; ++kq) v += gb[kq * 1056 + base];
            s[q] = v;
        }
        float ii = sigf(s[0]), ff = sigf(s[1]), oo = sigf(s[2]), gg = tanhf(s[3]);
        C[g] = ff * C[g] + ii * gg;
        float h = oo * tanhf(C[g]);
        int grow = g * 32 + row;
        g_Hbuf[(t & 1) ^ 1][grow * 1024 + (cta << 3) + j] = __float2half(h);
        if (t == LSEQ - 1) out[grow * 1024 + (cta << 3) + j] = h;
    };

    // prologue: both groups' H[0] loads in flight
    issue(0, 0);
    issue(1, 0);

    for (int t = 0; t < LSEQ; ++t) {
        // gx for this step, both groups (independent of barriers; hides under waits)
        const float* gxt = gxbase + (size_t)t * G4 * NB;
        float gxr[2][4];
#pragma unroll
        for (int g = 0; g < 2; ++g)
#pragma unroll
            for (int q = 0; q < 4; ++q)
                gxr[g][q] = gxt[(g * 32 + row) * 32 + q * 8 + j];

        float acc[4][4];

        // ---------- group 0 ----------
        cp_wait<1>();                              // g0 H staged
        __syncwarp();
#pragma unroll
        for (int a = 0; a < 4; ++a)
#pragma unroll
            for (int b = 0; b < 4; ++b) acc[a][b] = 0.0f;
        mmaphase(Hs0, acc);
        __syncthreads();                           // Hs0 reads done (gsm0 aliases)
        storegsm(gsm0, acc);
        __syncthreads();
        cell(0, gxr[0], t);                        // C,H update g0
        __threadfence();
        __syncthreads();
        if (tid == 0) atomicAdd(&g_bar[t], 1);     // arrive bar0[t]

        // ---------- group 1 ----------
        cp_wait<0>();                              // g1 H staged (landed long ago)
        __syncwarp();
#pragma unroll
        for (int a = 0; a < 4; ++a)
#pragma unroll
            for (int b = 0; b < 4; ++b) acc[a][b] = 0.0f;
        mmaphase(Hs1, acc);
        __syncthreads();                           // Hs1 reads done

        // poll bar0 (arrivals spread covered by g1 mma) + refill Hs0 for t+1
        if (t + 1 < LSEQ && tid == 0) {
            while (*(volatile int*)&g_bar[t] < NCTA) { }
        }
        __syncthreads();
        if (t + 1 < LSEQ) issue(0, (t + 1) & 1);   // writes Hs0 (gsm0 reads done)

        storegsm(gsm1, acc);
        __syncthreads();
        cell(1, gxr[1], t);
        __threadfence();
        __syncthreads();
        if (tid == 0) {
            atomicAdd(&g_bar[LSEQ + t], 1);        // arrive bar1[t]
            if (t + 1 < LSEQ)
                while (*(volatile int*)&g_bar[LSEQ + t] < NCTA) { }
        }
        __syncthreads();
        if (t + 1 < LSEQ) issue(1, (t + 1) & 1);
    }
}

// ---------------- launch ----------------------------------------------------------
extern "C" void kernel_launch(void* const* d_in, const int* in_sizes, int n_in,
                              void* d_out, int out_size) {
    (void)in_sizes; (void)n_in; (void)out_size;
    const int*   X  = (const int*)d_in[0];
    const float* E  = (const float*)d_in[1];
    const float* W  = (const float*)d_in[2];
    const float* Wb = (const float*)d_in[3];
    float* out = (float*)d_out;

    cudaFuncSetAttribute(k_rec, cudaFuncAttributeMaxDynamicSharedMemorySize, SMEM_REC);
    cudaFuncSetAttribute(k_gx, cudaFuncAttributeMaxDynamicSharedMemorySize, GX_SMEM);

    k_cvt_e<<<2048, 256>>>(E);
    k_pack<<<1024, 256>>>(W, Wb);
    k_gx<<<dim3(32, 256), 256, GX_SMEM>>>(X);
    k_rec<<<NCTA, 256, SMEM_REC>>>(W, out);
}

// round 9
// speedup vs baseline: 1.2800x; 1.2800x over previous
#include <cuda_runtime.h>
#include <cuda_fp16.h>
#include <cstdint>

#define VOCABSZ 32000
#define EMBD    1024
#define HID     1024
#define G4      4096
#define NB      64
#define LSEQ    512
#define NCTA    128
#define NGRP    2          // batch groups
#define CPG     64         // CTAs per group
#define ROWS    32         // batch rows per group

// ---------------- device scratch (static; no cudaMalloc allowed) ----------------
__device__ __half g_Eb[(size_t)VOCABSZ * EMBD];          // E as fp16 (64 MB)
__device__ __half g_Bx[(size_t)G4 * 1024];               // W_x^T, [colp][k], gate-permuted (8 MB)
__device__ float  g_bias[G4];                            // permuted bias
__device__ float  g_Gx[(size_t)LSEQ * G4 * NB];          // x-gates, [t][c][n][loc64]
__device__ __half g_Hbuf[2][NB * HID];                   // H double buffer (fp16)
__device__ int    g_bar[NGRP * LSEQ];                    // per-group per-step counters

// gate-column permutation: colp = c*64 + loc ; gate = loc>>4, unit = c*16 + (loc&15)
__device__ __forceinline__ int perm_row(int colp) {
    int c = colp >> 6, loc = colp & 63;
    return ((loc >> 4) << 10) + c * 16 + (loc & 15);
}

// ---------------- mma / ldmatrix / cp.async helpers -----------------------------
__device__ __forceinline__ unsigned smem_u32(const void* p) {
    return (unsigned)__cvta_generic_to_shared(p);
}
__device__ __forceinline__ void ldmatrix_x4(unsigned* r, unsigned addr) {
    asm volatile("ldmatrix.sync.aligned.m8n8.x4.shared.b16 {%0,%1,%2,%3}, [%4];"
                 : "=r"(r[0]), "=r"(r[1]), "=r"(r[2]), "=r"(r[3]) : "r"(addr));
}
__device__ __forceinline__ void ldmatrix_x2(unsigned* r, unsigned addr) {
    asm volatile("ldmatrix.sync.aligned.m8n8.x2.shared.b16 {%0,%1}, [%2];"
                 : "=r"(r[0]), "=r"(r[1]) : "r"(addr));
}
__device__ __forceinline__ void mma16816(float* d, const unsigned* a, unsigned b0, unsigned b1) {
    asm volatile("mma.sync.aligned.m16n8k16.row.col.f32.f16.f16.f32 "
                 "{%0,%1,%2,%3}, {%4,%5,%6,%7}, {%8,%9}, {%0,%1,%2,%3};"
                 : "+f"(d[0]), "+f"(d[1]), "+f"(d[2]), "+f"(d[3])
                 : "r"(a[0]), "r"(a[1]), "r"(a[2]), "r"(a[3]), "r"(b0), "r"(b1));
}
__device__ __forceinline__ void cp16(void* s, const void* g) {
    asm volatile("cp.async.cg.shared.global [%0], [%1], 16;"
                 :: "r"(smem_u32(s)), "l"(g) : "memory");
}
__device__ __forceinline__ void cp_commit() { asm volatile("cp.async.commit_group;" ::: "memory"); }
template <int N>
__device__ __forceinline__ void cp_wait() { asm volatile("cp.async.wait_group %0;" :: "n"(N) : "memory"); }

__device__ __forceinline__ void red_release(int* p, int v) {
    asm volatile("red.release.gpu.global.add.u32 [%0], %1;" :: "l"(p), "r"(v) : "memory");
}
__device__ __forceinline__ int ld_acquire(const int* p) {
    int v;
    asm volatile("ld.global.acquire.gpu.b32 %0, [%1];" : "=r"(v) : "l"(p) : "memory");
    return v;
}
__device__ __forceinline__ float sigf(float x) { return 1.0f / (1.0f + expf(-x)); }

// ---------------- prep: E -> fp16 ------------------------------------------------
__global__ __launch_bounds__(256) void k_cvt_e(const float* __restrict__ E) {
    size_t total8 = (size_t)VOCABSZ * EMBD / 8;
    size_t stride = (size_t)gridDim.x * blockDim.x;
    for (size_t i = (size_t)blockIdx.x * blockDim.x + threadIdx.x; i < total8; i += stride) {
        const float4* s = (const float4*)(E + i * 8);
        float4 v0 = s[0], v1 = s[1];
        __half2 h0 = __floats2half2_rn(v0.x, v0.y);
        __half2 h1 = __floats2half2_rn(v0.z, v0.w);
        __half2 h2 = __floats2half2_rn(v1.x, v1.y);
        __half2 h3 = __floats2half2_rn(v1.z, v1.w);
        uint4 o;
        o.x = *(unsigned*)&h0; o.y = *(unsigned*)&h1;
        o.z = *(unsigned*)&h2; o.w = *(unsigned*)&h3;
        ((uint4*)g_Eb)[i] = o;
    }
}

// ---------------- prep: pack Bx, bias, reset barriers & H0 -----------------------
__global__ __launch_bounds__(256) void k_pack(const float* __restrict__ W,
                                              const float* __restrict__ Wb) {
    int i0 = blockIdx.x * blockDim.x + threadIdx.x;
    int stride = gridDim.x * blockDim.x;
    for (int idx = i0; idx < G4 * 1024; idx += stride) {
        int colp = idx >> 10, k = idx & 1023;
        g_Bx[idx] = __float2half(W[(size_t)perm_row(colp) * 2048 + 1024 + k]);
    }
    for (int idx = i0; idx < G4; idx += stride) g_bias[idx] = Wb[perm_row(idx)];
    for (int idx = i0; idx < NGRP * LSEQ; idx += stride) g_bar[idx] = 0;
    for (int idx = i0; idx < NB * HID; idx += stride) g_Hbuf[0][idx] = __float2half(0.0f);
}

// ---------------- phase 1: Gx = embed(X) @ Wx^T + b (R7-proven) -------------------
#define GX_STG  4
#define GX_STR  40
#define GX_TILE (128 * GX_STR)
#define GX_SMEM (GX_STG * 2 * GX_TILE * 2)       // 81920 B

__global__ __launch_bounds__(256, 2) void k_gx(const int* __restrict__ X) {
    extern __shared__ __align__(16) __half dsm[];
    __half* As = dsm;
    __half* Bs = dsm + GX_STG * GX_TILE;
    __shared__ int   toks[128];
    __shared__ float bsm[128];

    int tid = threadIdx.x, lane = tid & 31, warp = tid >> 5;
    int wm = warp >> 1, wn = warp & 1;
    int mblk = blockIdx.y * 128, nblk = blockIdx.x * 128;

    if (tid < 128) {
        int m = mblk + tid;                      // m = t*64 + n
        toks[tid] = X[(m & 63) * LSEQ + (m >> 6)];
        bsm[tid] = g_bias[nblk + tid];
    }
    __syncthreads();

    auto issue = [&](int c) {
        __half* Ab = As + (c & (GX_STG - 1)) * GX_TILE;
        __half* Bb = Bs + (c & (GX_STG - 1)) * GX_TILE;
        int k0 = c * 32;
#pragma unroll
        for (int i = 0; i < 2; ++i) {
            int idx = tid + i * 256;
            int row = idx >> 2, q = idx & 3;
            cp16(Ab + row * GX_STR + q * 8,
                 &g_Eb[(size_t)toks[row] * EMBD + k0 + q * 8]);
        }
#pragma unroll
        for (int i = 0; i < 2; ++i) {
            int idx = tid + i * 256;
            int row = idx >> 2, q = idx & 3;
            cp16(Bb + row * GX_STR + q * 8,
                 &g_Bx[(size_t)(nblk + row) * 1024 + k0 + q * 8]);
        }
        cp_commit();
    };

    float acc[2][8][4];
#pragma unroll
    for (int a = 0; a < 2; ++a)
#pragma unroll
        for (int b = 0; b < 8; ++b)
#pragma unroll
            for (int c = 0; c < 4; ++c) acc[a][b][c] = 0.0f;

    issue(0); issue(1); issue(2);

    for (int c = 0; c < 32; ++c) {
        if (c < 30)       cp_wait<2>();
        else if (c == 30) cp_wait<1>();
        else              cp_wait<0>();
        __syncthreads();

        if (c + 3 < 32) issue(c + 3);

        const __half* Ab = As + (c & (GX_STG - 1)) * GX_TILE;
        const __half* Bb = Bs + (c & (GX_STG - 1)) * GX_TILE;
#pragma unroll
        for (int ks = 0; ks < 2; ++ks) {
            unsigned a[2][4];
#pragma unroll
            for (int mt = 0; mt < 2; ++mt)
                ldmatrix_x4(a[mt], smem_u32(Ab + (wm * 32 + mt * 16 + (lane & 15)) * GX_STR
                                               + ks * 16 + (lane >> 4) * 8));
#pragma unroll
            for (int nt = 0; nt < 8; ++nt) {
                unsigned b[2];
                ldmatrix_x2(b, smem_u32(Bb + (wn * 64 + nt * 8 + (lane & 7)) * GX_STR
                                           + ks * 16 + ((lane >> 3) & 1) * 8));
                mma16816(acc[0][nt], a[0], b[0], b[1]);
                mma16816(acc[1][nt], a[1], b[0], b[1]);
            }
        }
    }

    // epilogue: add bias, store Gx[t][c][n][loc64]
#pragma unroll
    for (int mt = 0; mt < 2; ++mt) {
#pragma unroll
        for (int nt = 0; nt < 8; ++nt) {
            int mrow = mblk + wm * 32 + mt * 16 + (lane >> 2);
            int cloc = wn * 64 + nt * 8 + ((lane & 3) << 1);
            int colp = nblk + cloc;
            float b0 = bsm[cloc], b1 = bsm[cloc + 1];
            const float* c = acc[mt][nt];
#pragma unroll
            for (int rr = 0; rr < 2; ++rr) {
                int m = mrow + rr * 8;
                int t = m >> 6, n = m & 63;
                size_t off = (((size_t)t * CPG + (colp >> 6)) * NB + n) * 64 + (colp & 63);
                float2 v; v.x = c[rr * 2] + b0; v.y = c[rr * 2 + 1] + b1;
                *(float2*)&g_Gx[off] = v;
            }
        }
    }
}

// ---------------- phase 2: persistent recurrent kernel ---------------------------
// R7 dataflow (2 groups x 64 CTAs, CTA owns 64 gate cols, warp = (wk, wn)) with:
//  - de-aliased gsm (no alias-protection sync)
//  - red.release arrival / all-lane ld.acquire poll (no membar, no wake sync)
//  - 2-chunk H refill with mma started after first chunk
#define HS_STRIDE 1032
#define SM_HS 0
#define SM_WS (ROWS * HS_STRIDE * 2)               // 66048
#define SM_GS (SM_WS + 64 * HS_STRIDE * 2)         // 198144
#define SMEM_REC (SM_GS + 4 * 32 * 65 * 4)         // 231424

__global__ void __launch_bounds__(256, 1) k_rec(const float* __restrict__ W,
                                                float* __restrict__ out) {
    extern __shared__ __align__(16) char smem[];
    __half (*Hs)[HS_STRIDE] = (__half(*)[HS_STRIDE])(smem + SM_HS);   // [32][1032]
    __half (*Ws)[HS_STRIDE] = (__half(*)[HS_STRIDE])(smem + SM_WS);   // [64][1032]
    float* gsm = (float*)(smem + SM_GS);           // [4][32][65] floats (dedicated)

    int g   = blockIdx.x >> 6;                     // group 0/1
    int c   = blockIdx.x & 63;                     // CTA index within group
    int tid = threadIdx.x, lane = tid & 31, warp = tid >> 5;
    int wk  = warp >> 1;                           // K-quarter 0..3
    int wn  = warp & 1;                            // n-half 0..1
    int cb  = wk * 256;

    // resident weight slice: Ws[loc][k] = W[(loc>>4)*1024 + c*16 + (loc&15)][k]
    for (int idx = tid; idx < 64 * 1024; idx += 256) {
        int loc = idx >> 10, k = idx & 1023;
        int wrow = ((loc >> 4) << 10) + c * 16 + (loc & 15);
        Ws[loc][k] = __float2half(W[(size_t)wrow * 2048 + k]);
    }
    __syncthreads();

    // elementwise ownership: em = batch row (0..31), units ej0, ej0+1 (of 16)
    int em = tid >> 3, ej0 = (tid & 7) * 2;
    float C0 = 0.0f, C1 = 0.0f;
    const float* gxbase = g_Gx + ((size_t)c * NB + g * ROWS + em) * 64 + ej0;
    int* barbase = &g_bar[g * LSEQ];

    // warp-private refill: 64-col chunk ch (0/1) of own 128 cols at K base cb
    auto issue_chunk = [&](int tpar, int ch) {
        const __half* Hg = g_Hbuf[tpar] + (size_t)g * ROWS * 1024;
        int colbase = cb + wn * 128 + ch * 64;
#pragma unroll
        for (int i = 0; i < 8; ++i) {
            int idx = i * 32 + lane;               // 0..255
            int row = idx >> 3;
            int col = colbase + (idx & 7) * 8;
            cp16(&Hs[row][col], Hg + row * 1024 + col);
        }
        cp_commit();
    };

    // 4 k-tiles of mma at K base k0base
    auto mma4 = [&](int k0base, float (*acc)[4]) {
#pragma unroll
        for (int kt = 0; kt < 4; ++kt) {
            int k0 = k0base + kt * 16;
            unsigned a[2][4];
#pragma unroll
            for (int mt = 0; mt < 2; ++mt)
                ldmatrix_x4(a[mt], smem_u32(&Hs[mt * 16 + (lane & 15)]
                                              [k0 + (lane >> 4) * 8]));
#pragma unroll
            for (int bg = 0; bg < 2; ++bg) {
                unsigned b[4];
                ldmatrix_x4(b, smem_u32(&Ws[wn * 32 + bg * 16 + ((lane >> 4) << 3) + (lane & 7)]
                                          [k0 + ((lane >> 3) & 1) * 8]));
#pragma unroll
                for (int mt = 0; mt < 2; ++mt) {
                    mma16816(acc[mt * 0 + bg * 2],     a[mt], b[0], b[1]);   // placeholder
                }
            }
        }
    };
    (void)mma4; // (not used; unrolled inline below for correct acc indexing)

    for (int t = 0; t < LSEQ; ++t) {
        // gx for this step (independent of barrier; hides LDG under poll)
        const float* gxp = gxbase + (size_t)t * CPG * NB * 64;
        float2 gxr[4];
#pragma unroll
        for (int q = 0; q < 4; ++q) gxr[q] = *(const float2*)(gxp + q * 16);

        // acquire-poll previous step's barrier (all lanes; warps proceed solo)
        if (t > 0) {
            const int* bp = barbase + (t - 1);
            while (ld_acquire(bp) < CPG) { }
        }
        __syncwarp();

        // refill own 128 cols in 2 chunks
        issue_chunk(t & 1, 0);
        issue_chunk(t & 1, 1);

        float acc[2][4][4];
#pragma unroll
        for (int a = 0; a < 2; ++a)
#pragma unroll
            for (int b = 0; b < 4; ++b)
#pragma unroll
                for (int cc = 0; cc < 4; ++cc) acc[a][b][cc] = 0.0f;

        // phase 0: own half (first 64 cols after chunk0, rest after chunk1)
#pragma unroll
        for (int sub = 0; sub < 2; ++sub) {
            if (sub == 0) cp_wait<1>(); else cp_wait<0>();
            __syncwarp();
            int k0b = cb + wn * 128 + sub * 64;
#pragma unroll
            for (int kt = 0; kt < 4; ++kt) {
                int k0 = k0b + kt * 16;
                unsigned a[2][4];
#pragma unroll
                for (int mt = 0; mt < 2; ++mt)
                    ldmatrix_x4(a[mt], smem_u32(&Hs[mt * 16 + (lane & 15)]
                                                  [k0 + (lane >> 4) * 8]));
#pragma unroll
                for (int bg = 0; bg < 2; ++bg) {
                    unsigned b[4];
                    ldmatrix_x4(b, smem_u32(&Ws[wn * 32 + bg * 16 + ((lane >> 4) << 3) + (lane & 7)]
                                              [k0 + ((lane >> 3) & 1) * 8]));
#pragma unroll
                    for (int mt = 0; mt < 2; ++mt) {
                        mma16816(acc[mt][bg * 2],     a[mt], b[0], b[1]);
                        mma16816(acc[mt][bg * 2 + 1], a[mt], b[2], b[3]);
                    }
                }
            }
        }

        // pair sync: partner's 128 cols now staged & stable
        asm volatile("bar.sync %0, 64;" :: "r"(1 + wk) : "memory");

        // phase 1: partner half
        {
            int k0b = cb + (1 - wn) * 128;
#pragma unroll 4
            for (int kt = 0; kt < 8; ++kt) {
                int k0 = k0b + kt * 16;
                unsigned a[2][4];
#pragma unroll
                for (int mt = 0; mt < 2; ++mt)
                    ldmatrix_x4(a[mt], smem_u32(&Hs[mt * 16 + (lane & 15)]
                                                  [k0 + (lane >> 4) * 8]));
#pragma unroll
                for (int bg = 0; bg < 2; ++bg) {
                    unsigned b[4];
                    ldmatrix_x4(b, smem_u32(&Ws[wn * 32 + bg * 16 + ((lane >> 4) << 3) + (lane & 7)]
                                              [k0 + ((lane >> 3) & 1) * 8]));
#pragma unroll
                    for (int mt = 0; mt < 2; ++mt) {
                        mma16816(acc[mt][bg * 2],     a[mt], b[0], b[1]);
                        mma16816(acc[mt][bg * 2 + 1], a[mt], b[2], b[3]);
                    }
                }
            }
        }

        // exchange: write K-partials (dedicated gsm, no alias sync needed)
        {
            float* gp = gsm + wk * (32 * 65);
            int mrow = lane >> 2;
            int ncol = wn * 32 + ((lane & 3) << 1);
#pragma unroll
            for (int mt = 0; mt < 2; ++mt)
#pragma unroll
                for (int ng = 0; ng < 4; ++ng) {
                    const float* cc = acc[mt][ng];
                    int m = mrow + mt * 16, n = ncol + ng * 8;
                    gp[m * 65 + n]           = cc[0];
                    gp[m * 65 + n + 1]       = cc[1];
                    gp[(m + 8) * 65 + n]     = cc[2];
                    gp[(m + 8) * 65 + n + 1] = cc[3];
                }
        }
        __syncthreads();

        // elementwise: 4-way K-reduction + LSTM cell
        float s[4][2];
#pragma unroll
        for (int q = 0; q < 4; ++q) {
            float v0 = gxr[q].x, v1 = gxr[q].y;
            int base = em * 65 + q * 16 + ej0;
#pragma unroll
            for (int kq = 0; kq < 4; ++kq) {
                v0 += gsm[kq * (32 * 65) + base];
                v1 += gsm[kq * (32 * 65) + base + 1];
            }
            s[q][0] = v0; s[q][1] = v1;
        }
        float i0 = sigf(s[0][0]), f0 = sigf(s[1][0]), o0 = sigf(s[2][0]), gg0 = tanhf(s[3][0]);
        float i1 = sigf(s[0][1]), f1 = sigf(s[1][1]), o1 = sigf(s[2][1]), gg1 = tanhf(s[3][1]);
        C0 = f0 * C0 + i0 * gg0;
        C1 = f1 * C1 + i1 * gg1;
        float h0 = o0 * tanhf(C0), h1 = o1 * tanhf(C1);

        __half* Hn = g_Hbuf[(t & 1) ^ 1];
        int grow = g * ROWS + em;
        int hcol = c * 16 + ej0;
        *(__half2*)(Hn + grow * 1024 + hcol) = __floats2half2_rn(h0, h1);
        if (t == LSEQ - 1) {
            float2 ov; ov.x = h0; ov.y = h1;
            *(float2*)(out + grow * 1024 + hcol) = ov;
        }

        // arrival: syncthreads (intra-CTA HB) + single gpu-scope release RMW
        __syncthreads();
        if (tid == 0 && t + 1 < LSEQ) red_release(barbase + t, 1);
    }
}

// ---------------- launch ----------------------------------------------------------
extern "C" void kernel_launch(void* const* d_in, const int* in_sizes, int n_in,
                              void* d_out, int out_size) {
    (void)in_sizes; (void)n_in; (void)out_size;
    const int*   X  = (const int*)d_in[0];
    const float* E  = (const float*)d_in[1];
    const float* W  = (const float*)d_in[2];
    const float* Wb = (const float*)d_in[3];
    float* out = (float*)d_out;

    cudaFuncSetAttribute(k_rec, cudaFuncAttributeMaxDynamicSharedMemorySize, SMEM_REC);
    cudaFuncSetAttribute(k_gx, cudaFuncAttributeMaxDynamicSharedMemorySize, GX_SMEM);

    k_cvt_e<<<2048, 256>>>(E);
    k_pack<<<1024, 256>>>(W, Wb);
    k_gx<<<dim3(32, 256), 256, GX_SMEM>>>(X);
    k_rec<<<NCTA, 256, SMEM_REC>>>(W, out);
}

// round 10
// speedup vs baseline: 1.3060x; 1.0203x over previous
#include <cuda_runtime.h>
#include <cuda_fp16.h>
#include <cstdint>

#define VOCABSZ 32000
#define EMBD    1024
#define HID     1024
#define G4      4096
#define NB      64
#define LSEQ    512
#define NCTA    128
#define NGRP    2          // batch groups
#define CPG     64         // CTAs per group
#define ROWS    32         // batch rows per group

// ---------------- device scratch (static; no cudaMalloc allowed) ----------------
__device__ __half g_Eb[(size_t)VOCABSZ * EMBD];          // E as fp16 (64 MB)
__device__ __half g_Bx[(size_t)G4 * 1024];               // W_x^T, [colp][k], gate-permuted (8 MB)
__device__ float  g_bias[G4];                            // permuted bias
__device__ float  g_Gx[(size_t)LSEQ * G4 * NB];          // x-gates, [t][c][n][loc64]
__device__ __half g_Hbuf[2][NB * HID];                   // H double buffer (fp16)
__device__ int    g_bar[NGRP * LSEQ * 4];                // per-group per-step per-quarter

// gate-column permutation: colp = c*64 + loc ; gate = loc>>4, unit = c*16 + (loc&15)
__device__ __forceinline__ int perm_row(int colp) {
    int c = colp >> 6, loc = colp & 63;
    return ((loc >> 4) << 10) + c * 16 + (loc & 15);
}

// ---------------- mma / ldmatrix / cp.async helpers -----------------------------
__device__ __forceinline__ unsigned smem_u32(const void* p) {
    return (unsigned)__cvta_generic_to_shared(p);
}
__device__ __forceinline__ void ldmatrix_x4(unsigned* r, unsigned addr) {
    asm volatile("ldmatrix.sync.aligned.m8n8.x4.shared.b16 {%0,%1,%2,%3}, [%4];"
                 : "=r"(r[0]), "=r"(r[1]), "=r"(r[2]), "=r"(r[3]) : "r"(addr));
}
__device__ __forceinline__ void ldmatrix_x2(unsigned* r, unsigned addr) {
    asm volatile("ldmatrix.sync.aligned.m8n8.x2.shared.b16 {%0,%1}, [%2];"
                 : "=r"(r[0]), "=r"(r[1]) : "r"(addr));
}
__device__ __forceinline__ void mma16816(float* d, const unsigned* a, unsigned b0, unsigned b1) {
    asm volatile("mma.sync.aligned.m16n8k16.row.col.f32.f16.f16.f32 "
                 "{%0,%1,%2,%3}, {%4,%5,%6,%7}, {%8,%9}, {%0,%1,%2,%3};"
                 : "+f"(d[0]), "+f"(d[1]), "+f"(d[2]), "+f"(d[3])
                 : "r"(a[0]), "r"(a[1]), "r"(a[2]), "r"(a[3]), "r"(b0), "r"(b1));
}
__device__ __forceinline__ void cp16(void* s, const void* g) {
    asm volatile("cp.async.cg.shared.global [%0], [%1], 16;"
                 :: "r"(smem_u32(s)), "l"(g) : "memory");
}
__device__ __forceinline__ void cp_commit() { asm volatile("cp.async.commit_group;" ::: "memory"); }
template <int N>
__device__ __forceinline__ void cp_wait() { asm volatile("cp.async.wait_group %0;" :: "n"(N) : "memory"); }

__device__ __forceinline__ void red_release(int* p, int v) {
    asm volatile("red.release.gpu.global.add.u32 [%0], %1;" :: "l"(p), "r"(v) : "memory");
}
__device__ __forceinline__ int ld_acquire(const int* p) {
    int v;
    asm volatile("ld.global.acquire.gpu.b32 %0, [%1];" : "=r"(v) : "l"(p) : "memory");
    return v;
}
__device__ __forceinline__ float sigf(float x) { return 1.0f / (1.0f + expf(-x)); }

// ---------------- prep: E -> fp16 ------------------------------------------------
__global__ __launch_bounds__(256) void k_cvt_e(const float* __restrict__ E) {
    size_t total8 = (size_t)VOCABSZ * EMBD / 8;
    size_t stride = (size_t)gridDim.x * blockDim.x;
    for (size_t i = (size_t)blockIdx.x * blockDim.x + threadIdx.x; i < total8; i += stride) {
        const float4* s = (const float4*)(E + i * 8);
        float4 v0 = s[0], v1 = s[1];
        __half2 h0 = __floats2half2_rn(v0.x, v0.y);
        __half2 h1 = __floats2half2_rn(v0.z, v0.w);
        __half2 h2 = __floats2half2_rn(v1.x, v1.y);
        __half2 h3 = __floats2half2_rn(v1.z, v1.w);
        uint4 o;
        o.x = *(unsigned*)&h0; o.y = *(unsigned*)&h1;
        o.z = *(unsigned*)&h2; o.w = *(unsigned*)&h3;
        ((uint4*)g_Eb)[i] = o;
    }
}

// ---------------- prep: pack Bx, bias, reset barriers & H0 -----------------------
__global__ __launch_bounds__(256) void k_pack(const float* __restrict__ W,
                                              const float* __restrict__ Wb) {
    int i0 = blockIdx.x * blockDim.x + threadIdx.x;
    int stride = gridDim.x * blockDim.x;
    for (int idx = i0; idx < G4 * 1024; idx += stride) {
        int colp = idx >> 10, k = idx & 1023;
        g_Bx[idx] = __float2half(W[(size_t)perm_row(colp) * 2048 + 1024 + k]);
    }
    for (int idx = i0; idx < G4; idx += stride) g_bias[idx] = Wb[perm_row(idx)];
    for (int idx = i0; idx < NGRP * LSEQ * 4; idx += stride) g_bar[idx] = 0;
    for (int idx = i0; idx < NB * HID; idx += stride) g_Hbuf[0][idx] = __float2half(0.0f);
}

// ---------------- phase 1: Gx = embed(X) @ Wx^T + b (R7-proven) -------------------
#define GX_STG  4
#define GX_STR  40
#define GX_TILE (128 * GX_STR)
#define GX_SMEM (GX_STG * 2 * GX_TILE * 2)       // 81920 B

__global__ __launch_bounds__(256, 2) void k_gx(const int* __restrict__ X) {
    extern __shared__ __align__(16) __half dsm[];
    __half* As = dsm;
    __half* Bs = dsm + GX_STG * GX_TILE;
    __shared__ int   toks[128];
    __shared__ float bsm[128];

    int tid = threadIdx.x, lane = tid & 31, warp = tid >> 5;
    int wm = warp >> 1, wn = warp & 1;
    int mblk = blockIdx.y * 128, nblk = blockIdx.x * 128;

    if (tid < 128) {
        int m = mblk + tid;                      // m = t*64 + n
        toks[tid] = X[(m & 63) * LSEQ + (m >> 6)];
        bsm[tid] = g_bias[nblk + tid];
    }
    __syncthreads();

    auto issue = [&](int c) {
        __half* Ab = As + (c & (GX_STG - 1)) * GX_TILE;
        __half* Bb = Bs + (c & (GX_STG - 1)) * GX_TILE;
        int k0 = c * 32;
#pragma unroll
        for (int i = 0; i < 2; ++i) {
            int idx = tid + i * 256;
            int row = idx >> 2, q = idx & 3;
            cp16(Ab + row * GX_STR + q * 8,
                 &g_Eb[(size_t)toks[row] * EMBD + k0 + q * 8]);
        }
#pragma unroll
        for (int i = 0; i < 2; ++i) {
            int idx = tid + i * 256;
            int row = idx >> 2, q = idx & 3;
            cp16(Bb + row * GX_STR + q * 8,
                 &g_Bx[(size_t)(nblk + row) * 1024 + k0 + q * 8]);
        }
        cp_commit();
    };

    float acc[2][8][4];
#pragma unroll
    for (int a = 0; a < 2; ++a)
#pragma unroll
        for (int b = 0; b < 8; ++b)
#pragma unroll
            for (int c = 0; c < 4; ++c) acc[a][b][c] = 0.0f;

    issue(0); issue(1); issue(2);

    for (int c = 0; c < 32; ++c) {
        if (c < 30)       cp_wait<2>();
        else if (c == 30) cp_wait<1>();
        else              cp_wait<0>();
        __syncthreads();

        if (c + 3 < 32) issue(c + 3);

        const __half* Ab = As + (c & (GX_STG - 1)) * GX_TILE;
        const __half* Bb = Bs + (c & (GX_STG - 1)) * GX_TILE;
#pragma unroll
        for (int ks = 0; ks < 2; ++ks) {
            unsigned a[2][4];
#pragma unroll
            for (int mt = 0; mt < 2; ++mt)
                ldmatrix_x4(a[mt], smem_u32(Ab + (wm * 32 + mt * 16 + (lane & 15)) * GX_STR
                                               + ks * 16 + (lane >> 4) * 8));
#pragma unroll
            for (int nt = 0; nt < 8; ++nt) {
                unsigned b[2];
                ldmatrix_x2(b, smem_u32(Bb + (wn * 64 + nt * 8 + (lane & 7)) * GX_STR
                                           + ks * 16 + ((lane >> 3) & 1) * 8));
                mma16816(acc[0][nt], a[0], b[0], b[1]);
                mma16816(acc[1][nt], a[1], b[0], b[1]);
            }
        }
    }

    // epilogue: add bias, store Gx[t][c][n][loc64]
#pragma unroll
    for (int mt = 0; mt < 2; ++mt) {
#pragma unroll
        for (int nt = 0; nt < 8; ++nt) {
            int mrow = mblk + wm * 32 + mt * 16 + (lane >> 2);
            int cloc = wn * 64 + nt * 8 + ((lane & 3) << 1);
            int colp = nblk + cloc;
            float b0 = bsm[cloc], b1 = bsm[cloc + 1];
            const float* c = acc[mt][nt];
#pragma unroll
            for (int rr = 0; rr < 2; ++rr) {
                int m = mrow + rr * 8;
                int t = m >> 6, n = m & 63;
                size_t off = (((size_t)t * CPG + (colp >> 6)) * NB + n) * 64 + (colp & 63);
                float2 v; v.x = c[rr * 2] + b0; v.y = c[rr * 2 + 1] + b1;
                *(float2*)&g_Gx[off] = v;
            }
        }
    }
}

// ---------------- phase 2: persistent recurrent kernel ---------------------------
// R7 dataflow (2 groups x 64 CTAs; CTA owns 64 gate cols = 16 units; warp (wk, wn))
// with PER-QUARTER sub-barriers: CTA c's H output lies entirely in quarter c>>4,
// so warp-pair wk waits only on bar[g][t-1][wk] (16 arrivals), then immediately
// refills + computes. Arrival = red.release by tid0 after post-cell syncthreads.
#define HS_STRIDE 1032
#define SM_HS 0
#define SM_WS (ROWS * HS_STRIDE * 2)               // 66048
#define SM_GS (SM_WS + 64 * HS_STRIDE * 2)         // 198144
#define SMEM_REC (SM_GS + 4 * 32 * 65 * 4)         // 231424

__global__ void __launch_bounds__(256, 1) k_rec(const float* __restrict__ W,
                                                float* __restrict__ out) {
    extern __shared__ __align__(16) char smem[];
    __half (*Hs)[HS_STRIDE] = (__half(*)[HS_STRIDE])(smem + SM_HS);   // [32][1032]
    __half (*Ws)[HS_STRIDE] = (__half(*)[HS_STRIDE])(smem + SM_WS);   // [64][1032]
    float* gsm = (float*)(smem + SM_GS);           // [4][32][65] floats (dedicated)

    int g   = blockIdx.x >> 6;                     // group 0/1
    int c   = blockIdx.x & 63;                     // CTA index within group
    int tid = threadIdx.x, lane = tid & 31, warp = tid >> 5;
    int wk  = warp >> 1;                           // K-quarter 0..3
    int wn  = warp & 1;                            // n-half 0..1
    int cb  = wk * 256;

    // resident weight slice: Ws[loc][k] = W[(loc>>4)*1024 + c*16 + (loc&15)][k]
    for (int idx = tid; idx < 64 * 1024; idx += 256) {
        int loc = idx >> 10, k = idx & 1023;
        int wrow = ((loc >> 4) << 10) + c * 16 + (loc & 15);
        Ws[loc][k] = __float2half(W[(size_t)wrow * 2048 + k]);
    }
    __syncthreads();

    // elementwise ownership: em = batch row (0..31), units ej0, ej0+1 (of 16)
    int em = tid >> 3, ej0 = (tid & 7) * 2;
    float C0 = 0.0f, C1 = 0.0f;
    const float* gxbase = g_Gx + ((size_t)c * NB + g * ROWS + em) * 64 + ej0;
    int* barbase = &g_bar[g * LSEQ * 4];
    int myq = c >> 4;                              // quarter this CTA's H lands in

    for (int t = 0; t < LSEQ; ++t) {
        // gx for this step (independent of barrier; LDG hides under poll)
        const float* gxp = gxbase + (size_t)t * CPG * NB * 64;
        float2 gxr[4];
#pragma unroll
        for (int q = 0; q < 4; ++q) gxr[q] = *(const float2*)(gxp + q * 16);

        // quarter-barrier: wait until the 16 producers of quarter wk finished t-1
        if (t > 0) {
            const int* bp = barbase + (t - 1) * 4 + wk;
            if (lane == 0) {
                while (ld_acquire(bp) < 16) { }
            }
            __syncwarp();
        }

        // refill own 128 cols (rows 0..31 x [cb + wn*128, +128)) — warp-private
        {
            const __half* Hg = g_Hbuf[t & 1] + (size_t)g * ROWS * 1024;
#pragma unroll
            for (int i = 0; i < 16; ++i) {
                int idx = i * 32 + lane;           // 0..511
                int row = idx >> 4;
                int col = cb + wn * 128 + (idx & 15) * 8;
                cp16(&Hs[row][col], Hg + row * 1024 + col);
            }
            cp_commit();
        }

        float acc[2][4][4];
#pragma unroll
        for (int a = 0; a < 2; ++a)
#pragma unroll
            for (int b = 0; b < 4; ++b)
#pragma unroll
                for (int cc = 0; cc < 4; ++cc) acc[a][b][cc] = 0.0f;

        cp_wait<0>();                              // own 8KB staged
        __syncwarp();

#pragma unroll
        for (int phase = 0; phase < 2; ++phase) {
            int half = phase ^ wn;                 // own half first
#pragma unroll 4
            for (int kt8 = 0; kt8 < 8; ++kt8) {
                int k0 = cb + half * 128 + kt8 * 16;
                unsigned a[2][4];
#pragma unroll
                for (int mt = 0; mt < 2; ++mt)
                    ldmatrix_x4(a[mt], smem_u32(&Hs[mt * 16 + (lane & 15)]
                                                  [k0 + (lane >> 4) * 8]));
#pragma unroll
                for (int bg = 0; bg < 2; ++bg) {
                    unsigned b[4];
                    ldmatrix_x4(b, smem_u32(&Ws[wn * 32 + bg * 16 + ((lane >> 4) << 3) + (lane & 7)]
                                              [k0 + ((lane >> 3) & 1) * 8]));
#pragma unroll
                    for (int mt = 0; mt < 2; ++mt) {
                        mma16816(acc[mt][bg * 2],     a[mt], b[0], b[1]);
                        mma16816(acc[mt][bg * 2 + 1], a[mt], b[2], b[3]);
                    }
                }
            }
            if (phase == 0) {                      // partner's half staged & stable
                asm volatile("bar.sync %0, 64;" :: "r"(1 + wk) : "memory");
            }
        }

        // exchange: write K-partials (dedicated gsm)
        {
            float* gp = gsm + wk * (32 * 65);
            int mrow = lane >> 2;
            int ncol = wn * 32 + ((lane & 3) << 1);
#pragma unroll
            for (int mt = 0; mt < 2; ++mt)
#pragma unroll
                for (int ng = 0; ng < 4; ++ng) {
                    const float* cc = acc[mt][ng];
                    int m = mrow + mt * 16, n = ncol + ng * 8;
                    gp[m * 65 + n]           = cc[0];
                    gp[m * 65 + n + 1]       = cc[1];
                    gp[(m + 8) * 65 + n]     = cc[2];
                    gp[(m + 8) * 65 + n + 1] = cc[3];
                }
        }
        __syncthreads();

        // elementwise: 4-way K-reduction + LSTM cell
        float s[4][2];
#pragma unroll
        for (int q = 0; q < 4; ++q) {
            float v0 = gxr[q].x, v1 = gxr[q].y;
            int base = em * 65 + q * 16 + ej0;
#pragma unroll
            for (int kq = 0; kq < 4; ++kq) {
                v0 += gsm[kq * (32 * 65) + base];
                v1 += gsm[kq * (32 * 65) + base + 1];
            }
            s[q][0] = v0; s[q][1] = v1;
        }
        float i0 = sigf(s[0][0]), f0 = sigf(s[1][0]), o0 = sigf(s[2][0]), gg0 = tanhf(s[3][0]);
        float i1 = sigf(s[0][1]), f1 = sigf(s[1][1]), o1 = sigf(s[2][1]), gg1 = tanhf(s[3][1]);
        C0 = f0 * C0 + i0 * gg0;
        C1 = f1 * C1 + i1 * gg1;
        float h0 = o0 * tanhf(C0), h1 = o1 * tanhf(C1);

        __half* Hn = g_Hbuf[(t & 1) ^ 1];
        int grow = g * ROWS + em;
        int hcol = c * 16 + ej0;
        *(__half2*)(Hn + grow * 1024 + hcol) = __floats2half2_rn(h0, h1);
        if (t == LSEQ - 1) {
            float2 ov; ov.x = h0; ov.y = h1;
            *(float2*)(out + grow * 1024 + hcol) = ov;
        }

        // arrive on this CTA's quarter counter (release orders the H stores,
        // which happen-before via the syncthreads)
        __syncthreads();
        if (tid == 0 && t + 1 < LSEQ)
            red_release(barbase + t * 4 + myq, 1);
    }
}

// ---------------- launch ----------------------------------------------------------
extern "C" void kernel_launch(void* const* d_in, const int* in_sizes, int n_in,
                              void* d_out, int out_size) {
    (void)in_sizes; (void)n_in; (void)out_size;
    const int*   X  = (const int*)d_in[0];
    const float* E  = (const float*)d_in[1];
    const float* W  = (const float*)d_in[2];
    const float* Wb = (const float*)d_in[3];
    float* out = (float*)d_out;

    cudaFuncSetAttribute(k_rec, cudaFuncAttributeMaxDynamicSharedMemorySize, SMEM_REC);
    cudaFuncSetAttribute(k_gx, cudaFuncAttributeMaxDynamicSharedMemorySize, GX_SMEM);

    k_cvt_e<<<2048, 256>>>(E);
    k_pack<<<1024, 256>>>(W, Wb);
    k_gx<<<dim3(32, 256), 256, GX_SMEM>>>(X);
    k_rec<<<NCTA, 256, SMEM_REC>>>(W, out);
}

// round 12
// speedup vs baseline: 1.3361x; 1.0231x over previous
#include <cuda_runtime.h>
#include <cuda_fp16.h>
#include <cstdint>

#define VOCABSZ 32000
#define EMBD    1024
#define HID     1024
#define G4      4096
#define NB      64
#define LSEQ    512
#define NCTA    128
#define NGRP    2          // batch groups
#define CPG     64         // CTAs per group
#define ROWS    32         // batch rows per group

// ---------------- device scratch (static; no cudaMalloc allowed) ----------------
__device__ __half g_Eb[(size_t)VOCABSZ * EMBD];          // E as fp16 (64 MB)
__device__ __half g_Bx[(size_t)G4 * 1024];               // W_x^T, [colp][k], gate-permuted (8 MB)
__device__ float  g_bias[G4];                            // permuted bias
__device__ float  g_Gx[(size_t)LSEQ * G4 * NB];          // x-gates, [t][c][n][loc64]
__device__ __half g_Hbuf[2][NB * HID];                   // H double buffer (fp16)
__device__ int    g_bar[NGRP * LSEQ];                    // per-group per-step counters

// gate-column permutation: colp = c*64 + loc ; gate = loc>>4, unit = c*16 + (loc&15)
__device__ __forceinline__ int perm_row(int colp) {
    int c = colp >> 6, loc = colp & 63;
    return ((loc >> 4) << 10) + c * 16 + (loc & 15);
}

// ---------------- mma / ldmatrix / cp.async helpers -----------------------------
__device__ __forceinline__ unsigned smem_u32(const void* p) {
    return (unsigned)__cvta_generic_to_shared(p);
}
__device__ __forceinline__ void ldmatrix_x4(unsigned* r, unsigned addr) {
    asm volatile("ldmatrix.sync.aligned.m8n8.x4.shared.b16 {%0,%1,%2,%3}, [%4];"
                 : "=r"(r[0]), "=r"(r[1]), "=r"(r[2]), "=r"(r[3]) : "r"(addr));
}
__device__ __forceinline__ void mma16816(float* d, const unsigned* a, unsigned b0, unsigned b1) {
    asm volatile("mma.sync.aligned.m16n8k16.row.col.f32.f16.f16.f32 "
                 "{%0,%1,%2,%3}, {%4,%5,%6,%7}, {%8,%9}, {%0,%1,%2,%3};"
                 : "+f"(d[0]), "+f"(d[1]), "+f"(d[2]), "+f"(d[3])
                 : "r"(a[0]), "r"(a[1]), "r"(a[2]), "r"(a[3]), "r"(b0), "r"(b1));
}
__device__ __forceinline__ void cp16(void* s, const void* g) {
    asm volatile("cp.async.cg.shared.global [%0], [%1], 16;"
                 :: "r"(smem_u32(s)), "l"(g) : "memory");
}
__device__ __forceinline__ void cp_commit() { asm volatile("cp.async.commit_group;" ::: "memory"); }
template <int N>
__device__ __forceinline__ void cp_wait() { asm volatile("cp.async.wait_group %0;" :: "n"(N) : "memory"); }

__device__ __forceinline__ void red_release(int* p, int v) {
    asm volatile("red.release.gpu.global.add.u32 [%0], %1;" :: "l"(p), "r"(v) : "memory");
}
__device__ __forceinline__ int ld_acquire(const int* p) {
    int v;
    asm volatile("ld.global.acquire.gpu.b32 %0, [%1];" : "=r"(v) : "l"(p) : "memory");
    return v;
}
__device__ __forceinline__ float sigf(float x) { return 1.0f / (1.0f + expf(-x)); }

// ---------------- prep: E -> fp16 ------------------------------------------------
__global__ __launch_bounds__(256) void k_cvt_e(const float* __restrict__ E) {
    size_t total8 = (size_t)VOCABSZ * EMBD / 8;
    size_t stride = (size_t)gridDim.x * blockDim.x;
    for (size_t i = (size_t)blockIdx.x * blockDim.x + threadIdx.x; i < total8; i += stride) {
        const float4* s = (const float4*)(E + i * 8);
        float4 v0 = s[0], v1 = s[1];
        __half2 h0 = __floats2half2_rn(v0.x, v0.y);
        __half2 h1 = __floats2half2_rn(v0.z, v0.w);
        __half2 h2 = __floats2half2_rn(v1.x, v1.y);
        __half2 h3 = __floats2half2_rn(v1.z, v1.w);
        uint4 o;
        o.x = *(unsigned*)&h0; o.y = *(unsigned*)&h1;
        o.z = *(unsigned*)&h2; o.w = *(unsigned*)&h3;
        ((uint4*)g_Eb)[i] = o;
    }
}

// ---------------- prep: pack Bx, bias, reset barriers & H0 -----------------------
__global__ __launch_bounds__(256) void k_pack(const float* __restrict__ W,
                                              const float* __restrict__ Wb) {
    int i0 = blockIdx.x * blockDim.x + threadIdx.x;
    int stride = gridDim.x * blockDim.x;
    for (int idx = i0; idx < G4 * 1024; idx += stride) {
        int colp = idx >> 10, k = idx & 1023;
        g_Bx[idx] = __float2half(W[(size_t)perm_row(colp) * 2048 + 1024 + k]);
    }
    for (int idx = i0; idx < G4; idx += stride) g_bias[idx] = Wb[perm_row(idx)];
    for (int idx = i0; idx < NGRP * LSEQ; idx += stride) g_bar[idx] = 0;
    for (int idx = i0; idx < NB * HID; idx += stride) g_Hbuf[0][idx] = __float2half(0.0f);
}

// ---------------- phase 1: Gx = embed(X) @ Wx^T + b -------------------------------
// R7 pipeline (4-stage cp.async, K-chunk 32, 2 CTAs/SM); B fragments now via
// ldmatrix.x4 (6 LDSM per k-slice instead of 10).
#define GX_STG  4
#define GX_STR  40
#define GX_TILE (128 * GX_STR)
#define GX_SMEM (GX_STG * 2 * GX_TILE * 2)       // 81920 B

__global__ __launch_bounds__(256, 2) void k_gx(const int* __restrict__ X) {
    extern __shared__ __align__(16) __half dsm[];
    __half* As = dsm;
    __half* Bs = dsm + GX_STG * GX_TILE;
    __shared__ int   toks[128];
    __shared__ float bsm[128];

    int tid = threadIdx.x, lane = tid & 31, warp = tid >> 5;
    int wm = warp >> 1, wn = warp & 1;
    int mblk = blockIdx.y * 128, nblk = blockIdx.x * 128;

    if (tid < 128) {
        int m = mblk + tid;                      // m = t*64 + n
        toks[tid] = X[(m & 63) * LSEQ + (m >> 6)];
        bsm[tid] = g_bias[nblk + tid];
    }
    __syncthreads();

    auto issue = [&](int c) {
        __half* Ab = As + (c & (GX_STG - 1)) * GX_TILE;
        __half* Bb = Bs + (c & (GX_STG - 1)) * GX_TILE;
        int k0 = c * 32;
#pragma unroll
        for (int i = 0; i < 2; ++i) {
            int idx = tid + i * 256;
            int row = idx >> 2, q = idx & 3;
            cp16(Ab + row * GX_STR + q * 8,
                 &g_Eb[(size_t)toks[row] * EMBD + k0 + q * 8]);
        }
#pragma unroll
        for (int i = 0; i < 2; ++i) {
            int idx = tid + i * 256;
            int row = idx >> 2, q = idx & 3;
            cp16(Bb + row * GX_STR + q * 8,
                 &g_Bx[(size_t)(nblk + row) * 1024 + k0 + q * 8]);
        }
        cp_commit();
    };

    float acc[2][8][4];
#pragma unroll
    for (int a = 0; a < 2; ++a)
#pragma unroll
        for (int b = 0; b < 8; ++b)
#pragma unroll
            for (int c = 0; c < 4; ++c) acc[a][b][c] = 0.0f;

    issue(0); issue(1); issue(2);

    for (int c = 0; c < 32; ++c) {
        if (c < 30)       cp_wait<2>();
        else if (c == 30) cp_wait<1>();
        else              cp_wait<0>();
        __syncthreads();

        if (c + 3 < 32) issue(c + 3);

        const __half* Ab = As + (c & (GX_STG - 1)) * GX_TILE;
        const __half* Bb = Bs + (c & (GX_STG - 1)) * GX_TILE;
#pragma unroll
        for (int ks = 0; ks < 2; ++ks) {
            unsigned a[2][4];
#pragma unroll
            for (int mt = 0; mt < 2; ++mt)
                ldmatrix_x4(a[mt], smem_u32(Ab + (wm * 32 + mt * 16 + (lane & 15)) * GX_STR
                                               + ks * 16 + (lane >> 4) * 8));
#pragma unroll
            for (int nt = 0; nt < 4; ++nt) {     // x4 B: 16 n-rows per ldsm
                unsigned b[4];
                ldmatrix_x4(b, smem_u32(Bb + (wn * 64 + nt * 16 + ((lane >> 4) << 3) + (lane & 7)) * GX_STR
                                           + ks * 16 + ((lane >> 3) & 1) * 8));
                mma16816(acc[0][nt * 2],     a[0], b[0], b[1]);
                mma16816(acc[1][nt * 2],     a[1], b[0], b[1]);
                mma16816(acc[0][nt * 2 + 1], a[0], b[2], b[3]);
                mma16816(acc[1][nt * 2 + 1], a[1], b[2], b[3]);
            }
        }
    }

    // epilogue: add bias, store Gx[t][c][n][loc64]
#pragma unroll
    for (int mt = 0; mt < 2; ++mt) {
#pragma unroll
        for (int nt = 0; nt < 8; ++nt) {
            int mrow = mblk + wm * 32 + mt * 16 + (lane >> 2);
            int cloc = wn * 64 + nt * 8 + ((lane & 3) << 1);
            int colp = nblk + cloc;
            float b0 = bsm[cloc], b1 = bsm[cloc + 1];
            const float* c = acc[mt][nt];
#pragma unroll
            for (int rr = 0; rr < 2; ++rr) {
                int m = mrow + rr * 8;
                int t = m >> 6, n = m & 63;
                size_t off = (((size_t)t * CPG + (colp >> 6)) * NB + n) * 64 + (colp & 63);
                float2 v; v.x = c[rr * 2] + b0; v.y = c[rr * 2 + 1] + b1;
                *(float2*)&g_Gx[off] = v;
            }
        }
    }
}

// ---------------- phase 2: persistent recurrent kernel ---------------------------
// R7 dataflow (2 groups x 64 CTAs; CTA owns 64 gate cols; warp (wk, wn)) with:
//  - arrival via red.release (no threadfence); tid0 acquire-poll; syncthreads wake
//  - H refill split into 2 x 64-col cp.async groups; mma starts after group 0
#define HS_STRIDE 1032
#define SM_HS 0
#define SM_WS (ROWS * HS_STRIDE * 2)               // 66048
#define SMEM_REC (SM_WS + 64 * HS_STRIDE * 2)      // 198144

__global__ void __launch_bounds__(256, 1) k_rec(const float* __restrict__ W,
                                                float* __restrict__ out) {
    extern __shared__ __align__(16) char smem[];
    __half (*Hs)[HS_STRIDE] = (__half(*)[HS_STRIDE])(smem + SM_HS);   // [32][1032]
    __half (*Ws)[HS_STRIDE] = (__half(*)[HS_STRIDE])(smem + SM_WS);   // [64][1032]
    float* gsm = (float*)(smem + SM_HS);           // [4][32][65] floats, aliases Hs

    int g   = blockIdx.x >> 6;                     // group 0/1
    int c   = blockIdx.x & 63;                     // CTA index within group
    int tid = threadIdx.x, lane = tid & 31, warp = tid >> 5;
    int wk  = warp >> 1;                           // K-quarter 0..3
    int wn  = warp & 1;                            // n-half 0..1
    int cb  = wk * 256;

    // resident weight slice: Ws[loc][k] = W[(loc>>4)*1024 + c*16 + (loc&15)][k]
    for (int idx = tid; idx < 64 * 1024; idx += 256) {
        int loc = idx >> 10, k = idx & 1023;
        int wrow = ((loc >> 4) << 10) + c * 16 + (loc & 15);
        Ws[loc][k] = __float2half(W[(size_t)wrow * 2048 + k]);
    }
    __syncthreads();

    // elementwise ownership: em = batch row (0..31), units ej0, ej0+1 (of 16)
    int em = tid >> 3, ej0 = (tid & 7) * 2;
    float C0 = 0.0f, C1 = 0.0f;
    const float* gxbase = g_Gx + ((size_t)c * NB + g * ROWS + em) * 64 + ej0;

    // prologue: gx for t=0
    float2 gxr[4];
#pragma unroll
    for (int q = 0; q < 4; ++q) gxr[q] = *(const float2*)(gxbase + q * 16);

    for (int t = 0; t < LSEQ; ++t) {
        // stage own 128 H cols in 2 x 64-col groups (rows 0..31)
        const __half* Hg = g_Hbuf[t & 1] + (size_t)g * ROWS * 1024;
#pragma unroll
        for (int ch = 0; ch < 2; ++ch) {
            int colbase = cb + wn * 128 + ch * 64;
#pragma unroll
            for (int i = 0; i < 8; ++i) {
                int idx = i * 32 + lane;           // 0..255
                int row = idx >> 3;
                int col = colbase + (idx & 7) * 8;
                cp16(&Hs[row][col], Hg + row * 1024 + col);
            }
            cp_commit();
        }

        float acc[2][4][4];
#pragma unroll
        for (int a = 0; a < 2; ++a)
#pragma unroll
            for (int b = 0; b < 4; ++b)
#pragma unroll
                for (int cc = 0; cc < 4; ++cc) acc[a][b][cc] = 0.0f;

        // phase 0: own half, overlapped with the second refill group
#pragma unroll
        for (int sub = 0; sub < 2; ++sub) {
            if (sub == 0) cp_wait<1>(); else cp_wait<0>();
            __syncwarp();
            int k0b = cb + wn * 128 + sub * 64;
#pragma unroll
            for (int kt = 0; kt < 4; ++kt) {
                int k0 = k0b + kt * 16;
                unsigned a[2][4];
#pragma unroll
                for (int mt = 0; mt < 2; ++mt)
                    ldmatrix_x4(a[mt], smem_u32(&Hs[mt * 16 + (lane & 15)]
                                                  [k0 + (lane >> 4) * 8]));
#pragma unroll
                for (int bg = 0; bg < 2; ++bg) {
                    unsigned b[4];
                    ldmatrix_x4(b, smem_u32(&Ws[wn * 32 + bg * 16 + ((lane >> 4) << 3) + (lane & 7)]
                                              [k0 + ((lane >> 3) & 1) * 8]));
#pragma unroll
                    for (int mt = 0; mt < 2; ++mt) {
                        mma16816(acc[mt][bg * 2],     a[mt], b[0], b[1]);
                        mma16816(acc[mt][bg * 2 + 1], a[mt], b[2], b[3]);
                    }
                }
            }
        }

        // pair sync: partner's 128 cols staged & stable
        asm volatile("bar.sync %0, 64;" :: "r"(1 + wk) : "memory");

        // phase 1: partner half
        {
            int k0b = cb + (1 - wn) * 128;
#pragma unroll 4
            for (int kt = 0; kt < 8; ++kt) {
                int k0 = k0b + kt * 16;
                unsigned a[2][4];
#pragma unroll
                for (int mt = 0; mt < 2; ++mt)
                    ldmatrix_x4(a[mt], smem_u32(&Hs[mt * 16 + (lane & 15)]
                                                  [k0 + (lane >> 4) * 8]));
#pragma unroll
                for (int bg = 0; bg < 2; ++bg) {
                    unsigned b[4];
                    ldmatrix_x4(b, smem_u32(&Ws[wn * 32 + bg * 16 + ((lane >> 4) << 3) + (lane & 7)]
                                              [k0 + ((lane >> 3) & 1) * 8]));
#pragma unroll
                    for (int mt = 0; mt < 2; ++mt) {
                        mma16816(acc[mt][bg * 2],     a[mt], b[0], b[1]);
                        mma16816(acc[mt][bg * 2 + 1], a[mt], b[2], b[3]);
                    }
                }
            }
        }

        // all Hs reads done before gsm (alias) is written
        __syncthreads();
        {
            float* gp = gsm + wk * (32 * 65);
            int mrow = lane >> 2;
            int ncol = wn * 32 + ((lane & 3) << 1);
#pragma unroll
            for (int mt = 0; mt < 2; ++mt)
#pragma unroll
                for (int ng = 0; ng < 4; ++ng) {
                    const float* cc = acc[mt][ng];
                    int m = mrow + mt * 16, n = ncol + ng * 8;
                    gp[m * 65 + n]           = cc[0];
                    gp[m * 65 + n + 1]       = cc[1];
                    gp[(m + 8) * 65 + n]     = cc[2];
                    gp[(m + 8) * 65 + n + 1] = cc[3];
                }
        }
        __syncthreads();

        // elementwise: 4-way K-reduction + LSTM cell
        float s[4][2];
#pragma unroll
        for (int q = 0; q < 4; ++q) {
            float v0 = gxr[q].x, v1 = gxr[q].y;
            int base = em * 65 + q * 16 + ej0;
#pragma unroll
            for (int kq = 0; kq < 4; ++kq) {
                v0 += gsm[kq * (32 * 65) + base];
                v1 += gsm[kq * (32 * 65) + base + 1];
            }
            s[q][0] = v0; s[q][1] = v1;
        }
        float i0 = sigf(s[0][0]), f0 = sigf(s[1][0]), o0 = sigf(s[2][0]), gg0 = tanhf(s[3][0]);
        float i1 = sigf(s[0][1]), f1 = sigf(s[1][1]), o1 = sigf(s[2][1]), gg1 = tanhf(s[3][1]);
        C0 = f0 * C0 + i0 * gg0;
        C1 = f1 * C1 + i1 * gg1;
        float h0 = o0 * tanhf(C0), h1 = o1 * tanhf(C1);

        __half* Hn = g_Hbuf[(t & 1) ^ 1];
        int grow = g * ROWS + em;
        int hcol = c * 16 + ej0;
        *(__half2*)(Hn + grow * 1024 + hcol) = __floats2half2_rn(h0, h1);
        if (t == LSEQ - 1) {
            float2 ov; ov.x = h0; ov.y = h1;
            *(float2*)(out + grow * 1024 + hcol) = ov;
        }

        // prefetch next step's gx (hides LDG under barrier)
        int tn = (t + 1 < LSEQ) ? (t + 1) : t;
        const float* gxp = gxbase + (size_t)tn * CPG * NB * 64;
#pragma unroll
        for (int q = 0; q < 4; ++q) gxr[q] = *(const float2*)(gxp + q * 16);

        // grid barrier: release-RMW arrival (no membar), tid0 acquire-poll,
        // CTA-wide wake via syncthreads (R7 shape)
        __syncthreads();
        if (tid == 0) {
            int* barp = &g_bar[g * LSEQ + t];
            red_release(barp, 1);
            while (ld_acquire(barp) < CPG) { }
        }
        __syncthreads();
    }
}

// ---------------- launch ----------------------------------------------------------
extern "C" void kernel_launch(void* const* d_in, const int* in_sizes, int n_in,
                              void* d_out, int out_size) {
    (void)in_sizes; (void)n_in; (void)out_size;
    const int*   X  = (const int*)d_in[0];
    const float* E  = (const float*)d_in[1];
    const float* W  = (const float*)d_in[2];
    const float* Wb = (const float*)d_in[3];
    float* out = (float*)d_out;

    cudaFuncSetAttribute(k_rec, cudaFuncAttributeMaxDynamicSharedMemorySize, SMEM_REC);
    cudaFuncSetAttribute(k_gx, cudaFuncAttributeMaxDynamicSharedMemorySize, GX_SMEM);

    k_cvt_e<<<2048, 256>>>(E);
    k_pack<<<1024, 256>>>(W, Wb);
    k_gx<<<dim3(32, 256), 256, GX_SMEM>>>(X);
    k_rec<<<NCTA, 256, SMEM_REC>>>(W, out);
}